// round 3
// baseline (speedup 1.0000x reference)
#include <cuda_runtime.h>
#include <math.h>

// ---------------------------------------------------------------------------
// InterPersonAttention, algebraically refactored:
//   F    = app @ We[:,6:]^T + be                      [512,256]
//   Wkq  = Wq^T @ Wk  (scaled by log2e/sqrt(128))     [256,256]
//   r    = app @ Wkq + rbias                          [512,256]
//   E[i,m,:] = relu(F[m,:] + We[:, :6] @ edges[i,m,:])   (never materialized)
//   S[i,m]   = r[i,:] . E[i,m,:]   (log2-scaled), diag excluded
//   P[i,:]   = softmax_m(S) @ E    (flash-style online softmax, fused)
//   out  = relu([app | P] @ [Wo1 | Wo2@Wv]^T + (Wo2@bv + bo))
// ---------------------------------------------------------------------------

#define NN 512
#define HID 256
#define ATT 128

__device__ float g_F[NN * HID];       // pre-relu feat part of E
__device__ float g_r[NN * HID];       // folded query vectors (log2e/sqrt scaled)
__device__ float g_Wkq[HID * HID];    // Wq^T @ Wk, scaled
__device__ float g_rbias[HID];
__device__ float g_bvo[HID];
__device__ float g_A4[NN * 512];      // [app | P] for final GEMM
__device__ float g_B4[HID * 512];     // [Wo1 | Wvo] for final GEMM

static __device__ __forceinline__ float relu(float x) { return fmaxf(x, 0.f); }

// ---------------------------------------------------------------------------
// Generic 64x64x16 tiled fp32 GEMM body.  C[M,N] = act(A @ opB + bias)
//   B_NT = true : B is [N,K] row-major (C += A[m,k]*B[n,k])
//   B_NT = false: B is [K,N] row-major (C += A[m,k]*B[k,n])
// Requires M,N multiples of 64 and K multiple of 16. A 16B-aligned rows,
// B rows 8B-aligned (NT uses float2 loads to tolerate odd ldb like 262).
// ---------------------------------------------------------------------------
template <bool B_NT, bool RELU>
static __device__ __forceinline__ void gemm_body(
    const float* __restrict__ A, int lda,
    const float* __restrict__ B, int ldb,
    const float* __restrict__ bias,
    float* __restrict__ C, int ldc, int K)
{
    __shared__ float As[16][64];
    __shared__ float Bs[16][64];
    const int tid = threadIdx.x;
    const int m0 = blockIdx.y * 64;
    const int n0 = blockIdx.x * 64;
    const int tx = tid & 15;        // 16 col groups of 4
    const int ty = tid >> 4;        // 16 row groups of 4
    const int arow = tid >> 2;      // 0..63
    const int akq  = (tid & 3) * 4; // 0,4,8,12

    float acc[4][4];
#pragma unroll
    for (int a = 0; a < 4; ++a)
#pragma unroll
        for (int b = 0; b < 4; ++b) acc[a][b] = 0.f;

    for (int k0 = 0; k0 < K; k0 += 16) {
        // A tile: [64 rows x 16 k], store transposed As[k][m]
        float4 av = *reinterpret_cast<const float4*>(
            A + (size_t)(m0 + arow) * lda + k0 + akq);
        As[akq + 0][arow] = av.x;
        As[akq + 1][arow] = av.y;
        As[akq + 2][arow] = av.z;
        As[akq + 3][arow] = av.w;
        if (B_NT) {
            const float* bp = B + (size_t)(n0 + arow) * ldb + k0 + akq;
            float2 b0 = *reinterpret_cast<const float2*>(bp);
            float2 b1 = *reinterpret_cast<const float2*>(bp + 2);
            Bs[akq + 0][arow] = b0.x;
            Bs[akq + 1][arow] = b0.y;
            Bs[akq + 2][arow] = b1.x;
            Bs[akq + 3][arow] = b1.y;
        } else {
            const int bk = tid >> 4;         // 0..15
            const int bn = (tid & 15) * 4;   // 0..60
            float4 bv = *reinterpret_cast<const float4*>(
                B + (size_t)(k0 + bk) * ldb + n0 + bn);
            *reinterpret_cast<float4*>(&Bs[bk][bn]) = bv;
        }
        __syncthreads();
#pragma unroll
        for (int k = 0; k < 16; ++k) {
            float4 a4 = *reinterpret_cast<const float4*>(&As[k][ty * 4]);
            float4 b4 = *reinterpret_cast<const float4*>(&Bs[k][tx * 4]);
            float a[4] = {a4.x, a4.y, a4.z, a4.w};
            float b[4] = {b4.x, b4.y, b4.z, b4.w};
#pragma unroll
            for (int im = 0; im < 4; ++im)
#pragma unroll
                for (int in = 0; in < 4; ++in)
                    acc[im][in] = fmaf(a[im], b[in], acc[im][in]);
        }
        __syncthreads();
    }

    float bi[4] = {0.f, 0.f, 0.f, 0.f};
    if (bias) {
#pragma unroll
        for (int in = 0; in < 4; ++in) bi[in] = bias[n0 + tx * 4 + in];
    }
#pragma unroll
    for (int im = 0; im < 4; ++im) {
        float4 o;
        o.x = acc[im][0] + bi[0];
        o.y = acc[im][1] + bi[1];
        o.z = acc[im][2] + bi[2];
        o.w = acc[im][3] + bi[3];
        if (RELU) { o.x = relu(o.x); o.y = relu(o.y); o.z = relu(o.z); o.w = relu(o.w); }
        *reinterpret_cast<float4*>(C + (size_t)(m0 + ty * 4 + im) * ldc + n0 + tx * 4) = o;
    }
}

// Thin wrappers binding __device__ scratch (host code cannot name __device__ vars)
__global__ __launch_bounds__(256) void k_gemm_Wvo(const float* __restrict__ Wo,
                                                  const float* __restrict__ Wv) {
    // Wvo[o,h] = sum_d Wo[o,256+d] * Wv[d,h]  -> g_B4[:, 256:]
    gemm_body<false, false>(Wo + 256, 512, Wv, HID, nullptr, g_B4 + 256, 512, HID);
}
__global__ __launch_bounds__(256) void k_gemm_F(const float* __restrict__ app,
                                                const float* __restrict__ We,
                                                const float* __restrict__ be) {
    // F[m,h] = sum_k app[m,k] * We[h,6+k] + be[h]
    gemm_body<true, false>(app, 256, We + 6, 262, be, g_F, HID, 256);
}
__global__ __launch_bounds__(256) void k_gemm_r(const float* __restrict__ app) {
    // r[n,h] = sum_k app[n,k] * Wkq[k,h] + rbias[h]
    gemm_body<false, false>(app, 256, g_Wkq, HID, g_rbias, g_r, HID, 256);
}
__global__ __launch_bounds__(256) void k_gemm_out(float* __restrict__ out,
                                                  const float* __restrict__ dummy) {
    // out = relu([app|P] @ [Wo1|Wvo]^T + bvo)
    (void)dummy;
    gemm_body<true, true>(g_A4, 512, g_B4, 512, g_bvo, out, HID, 512);
}

// ---------------------------------------------------------------------------
// Prep: Wkq = Wq^T @ Wk (scaled), rbias = bq @ Wk (scaled), bvo = Wo2@bv + bo
// Scale folds both 1/sqrt(ATT) and log2(e) so attention uses exp2f directly.
// ---------------------------------------------------------------------------
__global__ __launch_bounds__(256) void k_prep(const float* __restrict__ Wq,
                                              const float* __restrict__ Wk,
                                              const float* __restrict__ bq,
                                              const float* __restrict__ Wo,
                                              const float* __restrict__ bv,
                                              const float* __restrict__ bo) {
    const float SCALE = 1.4426950408889634f * 0.08838834764831845f; // log2e / sqrt(128)
    __shared__ float scol[ATT];
    const int b = blockIdx.x;
    const int tid = threadIdx.x;
    if (b < 256) {
        if (tid < ATT) scol[tid] = Wq[tid * 256 + b];
        __syncthreads();
        float acc = 0.f;
#pragma unroll 4
        for (int a = 0; a < ATT; ++a) acc = fmaf(scol[a], Wk[a * HID + tid], acc);
        g_Wkq[b * HID + tid] = acc * SCALE;
    } else if (b == 256) {
        if (tid < ATT) scol[tid] = bq[tid];
        __syncthreads();
        float acc = 0.f;
#pragma unroll 4
        for (int a = 0; a < ATT; ++a) acc = fmaf(scol[a], Wk[a * HID + tid], acc);
        g_rbias[tid] = acc * SCALE;
    } else {
        float acc = 0.f;
        const float* wrow = Wo + (size_t)tid * 512 + 256;
#pragma unroll 4
        for (int d = 0; d < HID; ++d) acc = fmaf(wrow[d], bv[d], acc);
        g_bvo[tid] = acc + bo[tid];
    }
}

// Copy app -> A4 left half, Wo1 -> B4 left half
__global__ __launch_bounds__(256) void k_copy(const float* __restrict__ app,
                                              const float* __restrict__ Wo) {
    const int idx = blockIdx.x * blockDim.x + threadIdx.x;
    if (idx < NN * 256) {
        const int n = idx >> 8, k = idx & 255;
        g_A4[(size_t)n * 512 + k] = app[idx];
    }
    if (idx < 256 * 256) {
        const int o = idx >> 8, k = idx & 255;
        g_B4[(size_t)o * 512 + k] = Wo[(size_t)o * 512 + k];
    }
}

// ---------------------------------------------------------------------------
// Fused attention: one CTA per node i (8 warps, 256 threads).
// Warp w handles m = w, w+8, ... ; lane l owns channels [8l, 8l+8).
// Per m: E_m = relu(F[m] + We6 @ edges[i,m]) in registers, s = r_i . E_m,
// online softmax (base 2), P accumulated; 8-warp partial-softmax merge.
// Writes P into g_A4[:, 256:].
// ---------------------------------------------------------------------------
__global__ __launch_bounds__(256) void k_attn(const float* __restrict__ edges,
                                              const float* __restrict__ We) {
    const int i = blockIdx.x;
    const int tid = threadIdx.x;
    const int w = tid >> 5, l = tid & 31;
    const int h0 = l * 8;

    // edge-projection coefficients for my 8 channels (48 regs, loaded once)
    float we6[8][6];
#pragma unroll
    for (int j = 0; j < 8; ++j)
#pragma unroll
        for (int c = 0; c < 6; ++c)
            we6[j][c] = We[(h0 + j) * 262 + c];

    float rr[8];
    {
        float4 r0 = *reinterpret_cast<const float4*>(g_r + (size_t)i * HID + h0);
        float4 r1 = *reinterpret_cast<const float4*>(g_r + (size_t)i * HID + h0 + 4);
        rr[0] = r0.x; rr[1] = r0.y; rr[2] = r0.z; rr[3] = r0.w;
        rr[4] = r1.x; rr[5] = r1.y; rr[6] = r1.z; rr[7] = r1.w;
    }

    float P[8] = {0.f, 0.f, 0.f, 0.f, 0.f, 0.f, 0.f, 0.f};
    float Mw = -1e30f, Zw = 0.f;

    const float* ep = edges + ((size_t)i * NN + w) * 6;
    const float* fp = g_F + (size_t)w * HID + h0;
    float2 e01 = *reinterpret_cast<const float2*>(ep);
    float2 e23 = *reinterpret_cast<const float2*>(ep + 2);
    float2 e45 = *reinterpret_cast<const float2*>(ep + 4);
    float4 f0 = *reinterpret_cast<const float4*>(fp);
    float4 f1 = *reinterpret_cast<const float4*>(fp + 4);

    for (int t = 0; t < 64; ++t) {
        const int m = w + (t << 3);
        float2 ce01 = e01, ce23 = e23, ce45 = e45;
        float4 cf0 = f0, cf1 = f1;
        if (t < 63) {  // prefetch next iteration (hide L2 latency)
            ep += 8 * 6;
            fp += 8 * HID;
            e01 = *reinterpret_cast<const float2*>(ep);
            e23 = *reinterpret_cast<const float2*>(ep + 2);
            e45 = *reinterpret_cast<const float2*>(ep + 4);
            f0 = *reinterpret_cast<const float4*>(fp);
            f1 = *reinterpret_cast<const float4*>(fp + 4);
        }
        float fv[8] = {cf0.x, cf0.y, cf0.z, cf0.w, cf1.x, cf1.y, cf1.z, cf1.w};
        float Ev[8];
        float s = 0.f;
#pragma unroll
        for (int j = 0; j < 8; ++j) {
            float g = fv[j];
            g = fmaf(we6[j][0], ce01.x, g);
            g = fmaf(we6[j][1], ce01.y, g);
            g = fmaf(we6[j][2], ce23.x, g);
            g = fmaf(we6[j][3], ce23.y, g);
            g = fmaf(we6[j][4], ce45.x, g);
            g = fmaf(we6[j][5], ce45.y, g);
            Ev[j] = fmaxf(g, 0.f);
            s = fmaf(rr[j], Ev[j], s);
        }
#pragma unroll
        for (int off = 16; off; off >>= 1)
            s += __shfl_xor_sync(0xffffffffu, s, off);
        if (m != i) {  // diagonal excluded (softmax -inf)
            const float newM = fmaxf(Mw, s);
            const float alpha = exp2f(Mw - newM);
            const float p = exp2f(s - newM);
            Zw = fmaf(Zw, alpha, p);
#pragma unroll
            for (int j = 0; j < 8; ++j) P[j] = fmaf(P[j], alpha, p * Ev[j]);
            Mw = newM;
        }
    }

    // merge the 8 per-warp partial softmaxes
    __shared__ float sM[8], sZ[8], sP[8][HID];
    if (l == 0) { sM[w] = Mw; sZ[w] = Zw; }
#pragma unroll
    for (int j = 0; j < 8; ++j) sP[w][h0 + j] = P[j];
    __syncthreads();

    float M = sM[0];
#pragma unroll
    for (int ww = 1; ww < 8; ++ww) M = fmaxf(M, sM[ww]);
    float Z = 0.f, acc = 0.f;
#pragma unroll
    for (int ww = 0; ww < 8; ++ww) {
        const float a = exp2f(sM[ww] - M);
        Z = fmaf(sZ[ww], a, Z);
        acc = fmaf(sP[ww][tid], a, acc);
    }
    g_A4[(size_t)i * 512 + 256 + tid] = acc / Z;
}

// ---------------------------------------------------------------------------
extern "C" void kernel_launch(void* const* d_in, const int* in_sizes, int n_in,
                              void* d_out, int out_size) {
    (void)in_sizes; (void)n_in; (void)out_size;
    const float* app  = (const float*)d_in[0];
    const float* edges = (const float*)d_in[1];
    const float* We   = (const float*)d_in[2];
    const float* be   = (const float*)d_in[3];
    const float* Wq   = (const float*)d_in[4];
    const float* bq   = (const float*)d_in[5];
    const float* Wk   = (const float*)d_in[6];
    // d_in[7] = bk: per-row-constant in softmax logits -> cancels, unused
    const float* Wv   = (const float*)d_in[8];
    const float* bv   = (const float*)d_in[9];
    const float* Wo   = (const float*)d_in[10];
    const float* bo   = (const float*)d_in[11];
    float* out = (float*)d_out;

    k_prep<<<258, 256>>>(Wq, Wk, bq, Wo, bv, bo);
    k_copy<<<512, 256>>>(app, Wo);
    k_gemm_Wvo<<<dim3(4, 4), 256>>>(Wo, Wv);
    k_gemm_F<<<dim3(4, 8), 256>>>(app, We, be);
    k_gemm_r<<<dim3(4, 8), 256>>>(app);
    k_attn<<<512, 256>>>(edges, We);
    k_gemm_out<<<dim3(4, 8), 256>>>(out, nullptr);
}

// round 4
// speedup vs baseline: 1.2988x; 1.2988x over previous
#include <cuda_runtime.h>
#include <math.h>

// ---------------------------------------------------------------------------
// InterPersonAttention, algebraically refactored:
//   F    = app @ We[:,6:]^T + be                      [512,256]
//   Wkq  = Wq^T @ Wk  (scaled by log2e/sqrt(128))     [256,256]
//   r    = app @ Wkq + rbias                          [512,256]
//   E[i,m,:] = relu(F[m,:] + We[:, :6] @ edges[i,m,:])   (never materialized)
//   S[i,m]   = r[i,:] . E[i,m,:]   (log2-scaled), diag excluded
//   P[i,:]   = softmax_m(S) @ E    (flash-style online softmax, fused)
//   out  = relu([app | P] @ [Wo1 | Wo2@Wv]^T + (Wo2@bv + bo))
//
// R3 changes (evidence: k_gemm_F 21.5us @ occ 12.4%, issue 27% -> latency
// bound at grid=32 with serialized mainloop):
//   - k_combo: prep + copy + Wvo-gemm + F-gemm fused into ONE 818-CTA launch
//   - gemm mainloop double-buffered (2-stage smem, reg prefetch, 1 sync/iter)
// ---------------------------------------------------------------------------

#define NN 512
#define HID 256
#define ATT 128

__device__ float g_F[NN * HID];       // pre-relu feat part of E
__device__ float g_r[NN * HID];       // folded query vectors (log2e/sqrt scaled)
__device__ float g_Wkq[HID * HID];    // Wq^T @ Wk, scaled
__device__ float g_rbias[HID];
__device__ float g_bvo[HID];
__device__ float g_A4[NN * 512];      // [app | P] for final GEMM
__device__ float g_B4[HID * 512];     // [Wo1 | Wvo] for final GEMM

static __device__ __forceinline__ float relu(float x) { return fmaxf(x, 0.f); }

// ---------------------------------------------------------------------------
// 64x64 tiled fp32 GEMM, double-buffered.  C[M,N] = act(A @ opB + bias)
//   B_NT = true : B is [N,K] row-major;  false: B is [K,N] row-major.
// M,N tiles of 64, K multiple of 16. A rows 16B-aligned; B rows 8B-aligned
// (NT path uses float2 loads to tolerate odd ldb like 262).
// Takes explicit (bx, by) so it can be dispatched from a combined kernel.
// ---------------------------------------------------------------------------
template <bool B_NT, bool RELU>
static __device__ __forceinline__ void gemm_body(
    int bx, int by,
    const float* __restrict__ A, int lda,
    const float* __restrict__ B, int ldb,
    const float* __restrict__ bias,
    float* __restrict__ C, int ldc, int K)
{
    __shared__ float As[2][16][64];
    __shared__ float Bs[2][16][64];
    const int tid = threadIdx.x;
    const int m0 = by * 64;
    const int n0 = bx * 64;
    const int tx = tid & 15;        // 16 col groups of 4
    const int ty = tid >> 4;        // 16 row groups of 4
    const int arow = tid >> 2;      // 0..63
    const int akq  = (tid & 3) * 4; // 0,4,8,12
    const int bk = tid >> 4;        // T-layout B loader: 0..15
    const int bn = (tid & 15) * 4;  // 0..60

    float acc[4][4];
#pragma unroll
    for (int a = 0; a < 4; ++a)
#pragma unroll
        for (int b = 0; b < 4; ++b) acc[a][b] = 0.f;

    const int T = K >> 4;

    // prologue: load tile 0 into regs
    float4 av = *reinterpret_cast<const float4*>(
        A + (size_t)(m0 + arow) * lda + akq);
    float2 nb0, nb1; float4 bv4;
    if (B_NT) {
        const float* bp = B + (size_t)(n0 + arow) * ldb + akq;
        nb0 = *reinterpret_cast<const float2*>(bp);
        nb1 = *reinterpret_cast<const float2*>(bp + 2);
    } else {
        bv4 = *reinterpret_cast<const float4*>(B + (size_t)bk * ldb + n0 + bn);
    }
    // store tile 0 into buffer 0
    As[0][akq + 0][arow] = av.x;
    As[0][akq + 1][arow] = av.y;
    As[0][akq + 2][arow] = av.z;
    As[0][akq + 3][arow] = av.w;
    if (B_NT) {
        Bs[0][akq + 0][arow] = nb0.x;
        Bs[0][akq + 1][arow] = nb0.y;
        Bs[0][akq + 2][arow] = nb1.x;
        Bs[0][akq + 3][arow] = nb1.y;
    } else {
        *reinterpret_cast<float4*>(&Bs[0][bk][bn]) = bv4;
    }
    __syncthreads();

    for (int t = 0; t < T; ++t) {
        const int cur = t & 1;
        if (t + 1 < T) {  // issue next-tile loads before compute (overlap)
            const int k0 = (t + 1) << 4;
            av = *reinterpret_cast<const float4*>(
                A + (size_t)(m0 + arow) * lda + k0 + akq);
            if (B_NT) {
                const float* bp = B + (size_t)(n0 + arow) * ldb + k0 + akq;
                nb0 = *reinterpret_cast<const float2*>(bp);
                nb1 = *reinterpret_cast<const float2*>(bp + 2);
            } else {
                bv4 = *reinterpret_cast<const float4*>(
                    B + (size_t)(k0 + bk) * ldb + n0 + bn);
            }
        }
#pragma unroll
        for (int k = 0; k < 16; ++k) {
            float4 a4 = *reinterpret_cast<const float4*>(&As[cur][k][ty * 4]);
            float4 b4 = *reinterpret_cast<const float4*>(&Bs[cur][k][tx * 4]);
            float a[4] = {a4.x, a4.y, a4.z, a4.w};
            float b[4] = {b4.x, b4.y, b4.z, b4.w};
#pragma unroll
            for (int im = 0; im < 4; ++im)
#pragma unroll
                for (int in = 0; in < 4; ++in)
                    acc[im][in] = fmaf(a[im], b[in], acc[im][in]);
        }
        if (t + 1 < T) {  // store prefetched tile into the other buffer
            const int nxt = cur ^ 1;
            As[nxt][akq + 0][arow] = av.x;
            As[nxt][akq + 1][arow] = av.y;
            As[nxt][akq + 2][arow] = av.z;
            As[nxt][akq + 3][arow] = av.w;
            if (B_NT) {
                Bs[nxt][akq + 0][arow] = nb0.x;
                Bs[nxt][akq + 1][arow] = nb0.y;
                Bs[nxt][akq + 2][arow] = nb1.x;
                Bs[nxt][akq + 3][arow] = nb1.y;
            } else {
                *reinterpret_cast<float4*>(&Bs[nxt][bk][bn]) = bv4;
            }
            __syncthreads();
        }
    }

    float bi[4] = {0.f, 0.f, 0.f, 0.f};
    if (bias) {
#pragma unroll
        for (int in = 0; in < 4; ++in) bi[in] = bias[n0 + tx * 4 + in];
    }
#pragma unroll
    for (int im = 0; im < 4; ++im) {
        float4 o;
        o.x = acc[im][0] + bi[0];
        o.y = acc[im][1] + bi[1];
        o.z = acc[im][2] + bi[2];
        o.w = acc[im][3] + bi[3];
        if (RELU) { o.x = relu(o.x); o.y = relu(o.y); o.z = relu(o.z); o.w = relu(o.w); }
        *reinterpret_cast<float4*>(C + (size_t)(m0 + ty * 4 + im) * ldc + n0 + tx * 4) = o;
    }
}

// ---------------------------------------------------------------------------
// k_combo: everything with no mutual dependency in ONE launch (818 CTAs):
//   blk [0,258):   prep  (Wkq cols / rbias / bvo)
//   blk [258,274): Wvo gemm  -> g_B4[:,256:]   (4x4 tiles)
//   blk [274,306): F gemm    -> g_F            (4x8 tiles)
//   blk [306,818): copy app->A4 left, Wo1->B4 left
// ---------------------------------------------------------------------------
__global__ __launch_bounds__(256) void k_combo(
    const float* __restrict__ app, const float* __restrict__ We,
    const float* __restrict__ be,  const float* __restrict__ Wq,
    const float* __restrict__ bq,  const float* __restrict__ Wo,
    const float* __restrict__ Wv,  const float* __restrict__ bv,
    const float* __restrict__ bo)
{
    const int blk = blockIdx.x;
    const int tid = threadIdx.x;
    if (blk < 258) {
        // ---- prep: Wkq = Wq^T @ Wk (scaled), rbias, bvo ----
        const float SCALE = 1.4426950408889634f * 0.08838834764831845f; // log2e/sqrt(128)
        __shared__ float scol[ATT];
        if (blk < 256) {
            if (tid < ATT) scol[tid] = Wq[tid * 256 + blk];
            __syncthreads();
            float acc = 0.f;
            const float* Wk = bq - 0;  // placeholder avoided; real Wk passed via bq? no
            (void)Wk;
            // NOTE: Wk is passed via the bq pointer slot? No — see launch: we pass
            // Wk through the 'bq' param? Keep signature honest: Wk comes in as 'bq'?
            acc = 0.f;
            // (real implementation below uses the wk pointer argument)
        }
        // -- the actual prep uses wk; fallthrough replaced below --
    }
    (void)0;
    // The real dispatch (prep needs Wk; see k_combo2). This stub never runs.
}

// k_combo2: actual combined kernel with full argument list.
__global__ __launch_bounds__(256) void k_combo2(
    const float* __restrict__ app, const float* __restrict__ We,
    const float* __restrict__ be,  const float* __restrict__ Wq,
    const float* __restrict__ bq,  const float* __restrict__ Wk,
    const float* __restrict__ Wv,  const float* __restrict__ bv,
    const float* __restrict__ Wo,  const float* __restrict__ bo)
{
    const int blk = blockIdx.x;
    const int tid = threadIdx.x;

    if (blk < 258) {
        // ---- prep ----
        const float SCALE = 1.4426950408889634f * 0.08838834764831845f;
        __shared__ float scol[ATT];
        if (blk < 256) {
            if (tid < ATT) scol[tid] = Wq[tid * 256 + blk];
            __syncthreads();
            float acc = 0.f;
#pragma unroll 4
            for (int a = 0; a < ATT; ++a) acc = fmaf(scol[a], Wk[a * HID + tid], acc);
            g_Wkq[blk * HID + tid] = acc * SCALE;
        } else if (blk == 256) {
            if (tid < ATT) scol[tid] = bq[tid];
            __syncthreads();
            float acc = 0.f;
#pragma unroll 4
            for (int a = 0; a < ATT; ++a) acc = fmaf(scol[a], Wk[a * HID + tid], acc);
            g_rbias[tid] = acc * SCALE;
        } else {
            float acc = 0.f;
            const float* wrow = Wo + (size_t)tid * 512 + 256;
#pragma unroll 4
            for (int d = 0; d < HID; ++d) acc = fmaf(wrow[d], bv[d], acc);
            g_bvo[tid] = acc + bo[tid];
        }
    } else if (blk < 274) {
        // ---- Wvo[o,h] = sum_d Wo[o,256+d]*Wv[d,h] -> g_B4[:,256:] ----
        const int b2 = blk - 258;           // 0..15 : 4x4 tiles
        gemm_body<false, false>(b2 & 3, b2 >> 2,
                                Wo + 256, 512, Wv, HID, nullptr,
                                g_B4 + 256, 512, HID);
    } else if (blk < 306) {
        // ---- F[m,h] = sum_k app[m,k]*We[h,6+k] + be[h] ----
        const int b2 = blk - 274;           // 0..31 : 4x8 tiles
        gemm_body<true, false>(b2 & 3, b2 >> 2,
                               app, 256, We + 6, 262, be,
                               g_F, HID, 256);
    } else {
        // ---- copy app -> A4 left half, Wo1 -> B4 left half ----
        const int idx = (blk - 306) * 256 + tid;
        if (idx < NN * 256) {
            const int n = idx >> 8, k = idx & 255;
            g_A4[(size_t)n * 512 + k] = app[idx];
        }
        if (idx < 256 * 256) {
            const int o = idx >> 8, k = idx & 255;
            g_B4[(size_t)o * 512 + k] = Wo[(size_t)o * 512 + k];
        }
    }
}

__global__ __launch_bounds__(256) void k_gemm_r(const float* __restrict__ app) {
    // r[n,h] = sum_k app[n,k] * Wkq[k,h] + rbias[h]   (4x8 tiles, grid 32)
    gemm_body<false, false>(blockIdx.x & 3, blockIdx.x >> 2,
                            app, 256, g_Wkq, HID, g_rbias, g_r, HID, 256);
}
__global__ __launch_bounds__(256) void k_gemm_out(float* __restrict__ out) {
    // out = relu([app|P] @ [Wo1|Wvo]^T + bvo)        (4x8 tiles, grid 32)
    gemm_body<true, true>(blockIdx.x & 3, blockIdx.x >> 2,
                          g_A4, 512, g_B4, 512, g_bvo, out, HID, 512);
}

// ---------------------------------------------------------------------------
// Fused attention: one CTA per node i (8 warps, 256 threads).
// Warp w handles m = w, w+8, ... ; lane l owns channels [8l, 8l+8).
// Per m: E_m = relu(F[m] + We6 @ edges[i,m]) in registers, s = r_i . E_m,
// online softmax (base 2), P accumulated; 8-warp partial-softmax merge.
// Writes P into g_A4[:, 256:].  (Unchanged from R2 -- it was NOT the top
// launch; measure before touching.)
// ---------------------------------------------------------------------------
__global__ __launch_bounds__(256) void k_attn(const float* __restrict__ edges,
                                              const float* __restrict__ We) {
    const int i = blockIdx.x;
    const int tid = threadIdx.x;
    const int w = tid >> 5, l = tid & 31;
    const int h0 = l * 8;

    float we6[8][6];
#pragma unroll
    for (int j = 0; j < 8; ++j)
#pragma unroll
        for (int c = 0; c < 6; ++c)
            we6[j][c] = We[(h0 + j) * 262 + c];

    float rr[8];
    {
        float4 r0 = *reinterpret_cast<const float4*>(g_r + (size_t)i * HID + h0);
        float4 r1 = *reinterpret_cast<const float4*>(g_r + (size_t)i * HID + h0 + 4);
        rr[0] = r0.x; rr[1] = r0.y; rr[2] = r0.z; rr[3] = r0.w;
        rr[4] = r1.x; rr[5] = r1.y; rr[6] = r1.z; rr[7] = r1.w;
    }

    float P[8] = {0.f, 0.f, 0.f, 0.f, 0.f, 0.f, 0.f, 0.f};
    float Mw = -1e30f, Zw = 0.f;

    const float* ep = edges + ((size_t)i * NN + w) * 6;
    const float* fp = g_F + (size_t)w * HID + h0;
    float2 e01 = *reinterpret_cast<const float2*>(ep);
    float2 e23 = *reinterpret_cast<const float2*>(ep + 2);
    float2 e45 = *reinterpret_cast<const float2*>(ep + 4);
    float4 f0 = *reinterpret_cast<const float4*>(fp);
    float4 f1 = *reinterpret_cast<const float4*>(fp + 4);

    for (int t = 0; t < 64; ++t) {
        const int m = w + (t << 3);
        float2 ce01 = e01, ce23 = e23, ce45 = e45;
        float4 cf0 = f0, cf1 = f1;
        if (t < 63) {
            ep += 8 * 6;
            fp += 8 * HID;
            e01 = *reinterpret_cast<const float2*>(ep);
            e23 = *reinterpret_cast<const float2*>(ep + 2);
            e45 = *reinterpret_cast<const float2*>(ep + 4);
            f0 = *reinterpret_cast<const float4*>(fp);
            f1 = *reinterpret_cast<const float4*>(fp + 4);
        }
        float fv[8] = {cf0.x, cf0.y, cf0.z, cf0.w, cf1.x, cf1.y, cf1.z, cf1.w};
        float Ev[8];
        float s = 0.f;
#pragma unroll
        for (int j = 0; j < 8; ++j) {
            float g = fv[j];
            g = fmaf(we6[j][0], ce01.x, g);
            g = fmaf(we6[j][1], ce01.y, g);
            g = fmaf(we6[j][2], ce23.x, g);
            g = fmaf(we6[j][3], ce23.y, g);
            g = fmaf(we6[j][4], ce45.x, g);
            g = fmaf(we6[j][5], ce45.y, g);
            Ev[j] = fmaxf(g, 0.f);
            s = fmaf(rr[j], Ev[j], s);
        }
#pragma unroll
        for (int off = 16; off; off >>= 1)
            s += __shfl_xor_sync(0xffffffffu, s, off);
        if (m != i) {
            const float newM = fmaxf(Mw, s);
            const float alpha = exp2f(Mw - newM);
            const float p = exp2f(s - newM);
            Zw = fmaf(Zw, alpha, p);
#pragma unroll
            for (int j = 0; j < 8; ++j) P[j] = fmaf(P[j], alpha, p * Ev[j]);
            Mw = newM;
        }
    }

    __shared__ float sM[8], sZ[8], sP[8][HID];
    if (l == 0) { sM[w] = Mw; sZ[w] = Zw; }
#pragma unroll
    for (int j = 0; j < 8; ++j) sP[w][h0 + j] = P[j];
    __syncthreads();

    float M = sM[0];
#pragma unroll
    for (int ww = 1; ww < 8; ++ww) M = fmaxf(M, sM[ww]);
    float Z = 0.f, acc = 0.f;
#pragma unroll
    for (int ww = 0; ww < 8; ++ww) {
        const float a = exp2f(sM[ww] - M);
        Z = fmaf(sZ[ww], a, Z);
        acc = fmaf(sP[ww][tid], a, acc);
    }
    g_A4[(size_t)i * 512 + 256 + tid] = acc / Z;
}

// ---------------------------------------------------------------------------
extern "C" void kernel_launch(void* const* d_in, const int* in_sizes, int n_in,
                              void* d_out, int out_size) {
    (void)in_sizes; (void)n_in; (void)out_size;
    const float* app   = (const float*)d_in[0];
    const float* edges = (const float*)d_in[1];
    const float* We    = (const float*)d_in[2];
    const float* be    = (const float*)d_in[3];
    const float* Wq    = (const float*)d_in[4];
    const float* bq    = (const float*)d_in[5];
    const float* Wk    = (const float*)d_in[6];
    // d_in[7] = bk: per-row-constant in softmax logits -> cancels, unused
    const float* Wv    = (const float*)d_in[8];
    const float* bv    = (const float*)d_in[9];
    const float* Wo    = (const float*)d_in[10];
    const float* bo    = (const float*)d_in[11];
    float* out = (float*)d_out;

    k_combo2<<<818, 256>>>(app, We, be, Wq, bq, Wk, Wv, bv, Wo, bo);
    k_gemm_r<<<32, 256>>>(app);
    k_attn<<<512, 256>>>(edges, We);
    k_gemm_out<<<32, 256>>>(out);
}